// round 1
// baseline (speedup 1.0000x reference)
#include <cuda_runtime.h>

// Analytic collapse of the QNN circuit:
//   z_i   = cos(x_i + theta_i)
//   out_w = prod_{i=0..w} z_i        (w = 1..9)
//   out_0 = prod_{i=1..9} z_i
//
// Pure streaming kernel: 2.62 MB in, 2.62 MB out. Shared-memory staging for
// coalesced float4 global traffic (row stride is 40 B, not 16B-aligned per row).

#define NQ       10
#define ROWS_PB  256          // rows (batch elements) per block
#define FLOATS_PB (ROWS_PB * NQ)   // 2560
#define VEC4_PB   (FLOATS_PB / 4)  // 640

__global__ __launch_bounds__(ROWS_PB) void qnn_expz_kernel(
    const float* __restrict__ x,
    const float* __restrict__ theta,
    float* __restrict__ out)
{
    __shared__ float s[FLOATS_PB];
    __shared__ float sth[NQ];

    const int tid = threadIdx.x;
    const long long base = (long long)blockIdx.x * FLOATS_PB;

    if (tid < NQ) sth[tid] = theta[tid];

    // Coalesced gather of 256 rows (2560 floats) into smem.
    const float4* __restrict__ xin = reinterpret_cast<const float4*>(x + base);
    float4* s4 = reinterpret_cast<float4*>(s);
#pragma unroll
    for (int i = 0; i < 3; i++) {
        int idx = tid + i * ROWS_PB;
        if (idx < VEC4_PB) s4[idx] = xin[idx];
    }
    __syncthreads();

    // Per-thread row compute.
    float z[NQ];
#pragma unroll
    for (int i = 0; i < NQ; i++)
        z[i] = cosf(s[tid * NQ + i] + sth[i]);

    float r[NQ];
    float p = z[0];
#pragma unroll
    for (int w = 1; w < NQ; w++) { p *= z[w]; r[w] = p; }

    float q = z[NQ - 1];
#pragma unroll
    for (int i = NQ - 2; i >= 1; i--) q *= z[i];
    r[0] = q;

    __syncthreads();
#pragma unroll
    for (int i = 0; i < NQ; i++) s[tid * NQ + i] = r[i];
    __syncthreads();

    // Coalesced scatter back to gmem.
    float4* __restrict__ o4 = reinterpret_cast<float4*>(out + base);
#pragma unroll
    for (int i = 0; i < 3; i++) {
        int idx = tid + i * ROWS_PB;
        if (idx < VEC4_PB) o4[idx] = s4[idx];
    }
}

extern "C" void kernel_launch(void* const* d_in, const int* in_sizes, int n_in,
                              void* d_out, int out_size)
{
    const float* x     = (const float*)d_in[0];   // (65536, 10) f32
    const float* theta = (const float*)d_in[1];   // (10,) f32
    float* out         = (float*)d_out;           // (65536, 10) f32

    const int batch  = in_sizes[0] / NQ;          // 65536
    const int blocks = batch / ROWS_PB;           // 256

    qnn_expz_kernel<<<blocks, ROWS_PB>>>(x, theta, out);
}

// round 2
// speedup vs baseline: 1.0386x; 1.0386x over previous
#include <cuda_runtime.h>

// Analytic collapse of the QNN circuit:
//   z_i   = cos(x_i + theta_i)
//   out_w = prod_{i=0..w} z_i        (w = 1..9)
//   out_0 = prod_{i=1..9} z_i
//
// Latency-optimized: no smem, no barriers. One row per thread, 5x LDG.64 in,
// 10x MUFU cos, log-depth product tree, 5x STG.64 out.

#define NQ      10
#define TPB     128

__global__ __launch_bounds__(TPB) void qnn_expz_kernel(
    const float* __restrict__ x,
    const float* __restrict__ theta,
    float* __restrict__ out)
{
    const long long row  = (long long)blockIdx.x * TPB + threadIdx.x;
    const long long base = row * NQ;

    // Row is 40 B => always 8-byte aligned. Load as 5 independent float2
    // (MLP = 5, front-batched).
    const float2* __restrict__ xin = reinterpret_cast<const float2*>(x + base);
    float2 v0 = xin[0];
    float2 v1 = xin[1];
    float2 v2 = xin[2];
    float2 v3 = xin[3];
    float2 v4 = xin[4];

    // theta: uniform across the warp, L1/L2 resident after first touch.
    float z[NQ];
    z[0] = __cosf(v0.x + __ldg(theta + 0));
    z[1] = __cosf(v0.y + __ldg(theta + 1));
    z[2] = __cosf(v1.x + __ldg(theta + 2));
    z[3] = __cosf(v1.y + __ldg(theta + 3));
    z[4] = __cosf(v2.x + __ldg(theta + 4));
    z[5] = __cosf(v2.y + __ldg(theta + 5));
    z[6] = __cosf(v3.x + __ldg(theta + 6));
    z[7] = __cosf(v3.y + __ldg(theta + 7));
    z[8] = __cosf(v4.x + __ldg(theta + 8));
    z[9] = __cosf(v4.y + __ldg(theta + 9));

    // Prefix products r[w] = z0*...*zw  (w>=1), with shallow dependency depth.
    float r1 = z[0] * z[1];          // p01
    float p23 = z[2] * z[3];
    float p45 = z[4] * z[5];
    float p67 = z[6] * z[7];
    float p89 = z[8] * z[9];

    float r2 = r1 * z[2];
    float r3 = r1 * p23;
    float r4 = r3 * z[4];
    float r5 = r3 * p45;
    float r6 = r5 * z[6];
    float r7 = r5 * p67;
    float r8 = r7 * z[8];
    float r9 = r7 * p89;

    // out0 = z1*...*z9 (suffix, excludes z0)
    float s14 = z[1] * p23 * z[4];   // z1..z4
    float r0  = s14 * p45 * p67 * p89 / (z[4] * z[4]); // careful: avoid this
    // -- the line above would divide; compute cleanly instead:
    // z1..z9 = z1 * (z2*z3) * (z4*z5) * (z6*z7) * (z8*z9)
    r0 = z[1] * p23;
    r0 = r0 * p45;
    r0 = r0 * p67;
    r0 = r0 * p89;

    float2* __restrict__ o2 = reinterpret_cast<float2*>(out + base);
    o2[0] = make_float2(r0, r1);
    o2[1] = make_float2(r2, r3);
    o2[2] = make_float2(r4, r5);
    o2[3] = make_float2(r6, r7);
    o2[4] = make_float2(r8, r9);
}

extern "C" void kernel_launch(void* const* d_in, const int* in_sizes, int n_in,
                              void* d_out, int out_size)
{
    const float* x     = (const float*)d_in[0];   // (65536, 10) f32
    const float* theta = (const float*)d_in[1];   // (10,) f32
    float* out         = (float*)d_out;           // (65536, 10) f32

    const int batch  = in_sizes[0] / NQ;          // 65536
    const int blocks = (batch + TPB - 1) / TPB;   // 512

    qnn_expz_kernel<<<blocks, TPB>>>(x, theta, out);
}